// round 2
// baseline (speedup 1.0000x reference)
#include <cuda_runtime.h>

#define BB   2
#define LL   2048
#define DIMK 1024
#define NH   16
#define DH   64
#define INNR 1024
#define ATT_SCALE 0.125f
#define EPSV 1e-10f

// Scratch (allocation-free): q,k,v in [b][h][l][dh], z in [b][l][inner]
__device__ __align__(256) float d_q[BB * NH * LL * DH];
__device__ __align__(256) float d_k[BB * NH * LL * DH];
__device__ __align__(256) float d_v[BB * NH * LL * DH];
__device__ __align__(256) float d_z[BB * LL * INNR];

// ---------------------------------------------------------------------------
// Kernel 1: QKV GEMM.  C[4096,3072] = x[4096,1024] @ W_qkv[1024,3072]
// 128x128x16 tiles, 256 threads, 8x8 microtile. Epilogue scatters to q/k/v.
// ---------------------------------------------------------------------------
__global__ __launch_bounds__(256) void qkv_gemm_kernel(
    const float* __restrict__ A, const float* __restrict__ W)
{
    __shared__ float As[16][128];   // As[k][m] (transposed)
    __shared__ float Bs[16][132];   // Bs[k][n] (padded)

    const int tid = threadIdx.x;
    const int tx = tid & 15, ty = tid >> 4;
    const int m0 = blockIdx.y * 128;
    const int n0 = blockIdx.x * 128;

    float acc[8][8] = {};

    for (int k0 = 0; k0 < DIMK; k0 += 16) {
        #pragma unroll
        for (int it = 0; it < 2; it++) {
            int s = tid + it * 256;
            int r = s >> 2, c4 = (s & 3) * 4;
            float4 f = *reinterpret_cast<const float4*>(&A[(m0 + r) * DIMK + k0 + c4]);
            As[c4 + 0][r] = f.x; As[c4 + 1][r] = f.y;
            As[c4 + 2][r] = f.z; As[c4 + 3][r] = f.w;
        }
        #pragma unroll
        for (int it = 0; it < 2; it++) {
            int s = tid + it * 256;
            int kk = s >> 5, n4 = (s & 31) * 4;
            *reinterpret_cast<float4*>(&Bs[kk][n4]) =
                *reinterpret_cast<const float4*>(&W[(k0 + kk) * 3072 + n0 + n4]);
        }
        __syncthreads();
        #pragma unroll 4
        for (int kk = 0; kk < 16; kk++) {
            float a[8], b[8];
            float4 a0 = *reinterpret_cast<float4*>(&As[kk][ty * 8]);
            float4 a1 = *reinterpret_cast<float4*>(&As[kk][ty * 8 + 4]);
            float4 b0 = *reinterpret_cast<float4*>(&Bs[kk][tx * 8]);
            float4 b1 = *reinterpret_cast<float4*>(&Bs[kk][tx * 8 + 4]);
            a[0]=a0.x; a[1]=a0.y; a[2]=a0.z; a[3]=a0.w;
            a[4]=a1.x; a[5]=a1.y; a[6]=a1.z; a[7]=a1.w;
            b[0]=b0.x; b[1]=b0.y; b[2]=b0.z; b[3]=b0.w;
            b[4]=b1.x; b[5]=b1.y; b[6]=b1.z; b[7]=b1.w;
            #pragma unroll
            for (int i = 0; i < 8; i++)
                #pragma unroll
                for (int j = 0; j < 8; j++)
                    acc[i][j] += a[i] * b[j];
        }
        __syncthreads();
    }

    // Epilogue: scatter into q/k/v head-major layout [b][h][l][dh]
    const int sec = n0 >> 10;                       // constant per CTA (128 | 1024)
    float* dst = (sec == 0) ? d_q : ((sec == 1) ? d_k : d_v);
    const int col0 = n0 + tx * 8;
    const int hh = (col0 >> 6) & (NH - 1);
    const int dd0 = col0 & (DH - 1);               // multiple of 8
    #pragma unroll
    for (int i = 0; i < 8; i++) {
        int row = m0 + ty * 8 + i;
        int bb = row >> 11, l = row & (LL - 1);
        float* p = dst + (((bb * NH + hh) * LL) + l) * DH + dd0;
        *reinterpret_cast<float4*>(p)     = make_float4(acc[i][0], acc[i][1], acc[i][2], acc[i][3]);
        *reinterpret_cast<float4*>(p + 4) = make_float4(acc[i][4], acc[i][5], acc[i][6], acc[i][7]);
    }
}

// ---------------------------------------------------------------------------
// Kernel 2: streaming masked attention (no running max needed: |s*scale| <~ 6).
// CTA = 128 q-rows of one (b,h). KV tiles of 64. Accumulates
//   o   += exp(s)*mask*v
//   Z   += exp(s)          (per row)
//   Zm  += exp(s)*mask     (per row)
// final: z = o / (Zm + eps*Z), written to [b][l][h*64+d].
// ---------------------------------------------------------------------------
#define SQ 132   // stride for qs / ps rows (128 + 4 pad)
#define SK 68    // stride for ks / vs rows (64 + 4 pad)
#define ATT_SMEM_FLOATS (64*SQ + 64*SK + 64*SK + 64*SQ + 256)

__global__ __launch_bounds__(256) void attn_kernel(const float* __restrict__ mask)
{
    extern __shared__ float sm[];
    float* qs  = sm;                 // [64][SQ]  qs[d][i]
    float* ks  = qs + 64 * SQ;       // [64][SK]  ks[d][j]
    float* vs  = ks + 64 * SK;       // [64][SK]  vs[j][d]
    float* ps  = vs + 64 * SK;       // [64][SQ]  ps[j][i]
    float* Zs  = ps + 64 * SQ;       // [128]
    float* Zms = Zs + 128;           // [128]

    const int tid = threadIdx.x;
    const int tj = tid & 15;         // 16 groups of 4 cols
    const int ti = tid >> 4;         // 16 groups of 8 rows
    const int i0 = blockIdx.x * 128;
    const int hh = blockIdx.y;
    const int bb = blockIdx.z;

    const float* qg = d_q + ((bb * NH + hh) * LL + i0) * DH;
    const float* kg = d_k + ((bb * NH + hh) * LL) * DH;
    const float* vg = d_v + ((bb * NH + hh) * LL) * DH;
    const float* mg = mask + (size_t)bb * LL * LL + (size_t)i0 * LL;

    if (tid < 128) { Zs[tid] = 0.f; Zms[tid] = 0.f; }

    // load q tile (128x64) transposed into qs[d][i]
    #pragma unroll
    for (int it = 0; it < 8; it++) {
        int s = tid + it * 256;
        int r = s >> 4, c4 = (s & 15) * 4;
        float4 f = *reinterpret_cast<const float4*>(qg + r * DH + c4);
        qs[(c4 + 0) * SQ + r] = f.x; qs[(c4 + 1) * SQ + r] = f.y;
        qs[(c4 + 2) * SQ + r] = f.z; qs[(c4 + 3) * SQ + r] = f.w;
    }

    float o[8][4] = {};
    float zl[8] = {};
    float zml[8] = {};

    for (int jb = 0; jb < LL / 64; jb++) {
        const int j0 = jb * 64;
        __syncthreads();
        // load k (transposed) and v (natural) tiles, 64x64 each
        #pragma unroll
        for (int it = 0; it < 4; it++) {
            int s = tid + it * 256;
            int r = s >> 4, c4 = (s & 15) * 4;
            float4 f = *reinterpret_cast<const float4*>(kg + (j0 + r) * DH + c4);
            ks[(c4 + 0) * SK + r] = f.x; ks[(c4 + 1) * SK + r] = f.y;
            ks[(c4 + 2) * SK + r] = f.z; ks[(c4 + 3) * SK + r] = f.w;
            float4 g = *reinterpret_cast<const float4*>(vg + (j0 + r) * DH + c4);
            *reinterpret_cast<float4*>(vs + r * SK + c4) = g;
        }
        __syncthreads();

        // S = q k^T : thread owns 8 rows x 4 cols
        float sf[8][4] = {};
        #pragma unroll 4
        for (int d = 0; d < 64; d++) {
            float4 qa = *reinterpret_cast<float4*>(qs + d * SQ + ti * 8);
            float4 qb = *reinterpret_cast<float4*>(qs + d * SQ + ti * 8 + 4);
            float4 kb = *reinterpret_cast<float4*>(ks + d * SK + tj * 4);
            float av[8] = {qa.x, qa.y, qa.z, qa.w, qb.x, qb.y, qb.z, qb.w};
            float bv[4] = {kb.x, kb.y, kb.z, kb.w};
            #pragma unroll
            for (int r = 0; r < 8; r++)
                #pragma unroll
                for (int c = 0; c < 4; c++)
                    sf[r][c] += av[r] * bv[c];
        }

        // exp, mask (vectorized), running sums, stage P^T for the PV GEMM
        #pragma unroll
        for (int r = 0; r < 8; r++) {
            const int il = ti * 8 + r;
            float4 mv = *reinterpret_cast<const float4*>(mg + (size_t)il * LL + j0 + tj * 4);
            float mvv[4] = {mv.x, mv.y, mv.z, mv.w};
            #pragma unroll
            for (int c = 0; c < 4; c++) {
                const int jl = tj * 4 + c;
                float e = __expf(sf[r][c] * ATT_SCALE);
                zl[r] += e;
                float p = e * mvv[c];
                zml[r] += p;
                ps[jl * SQ + il] = p;
            }
        }
        __syncthreads();

        // O += P @ V : thread owns 8 rows x 4 dh-cols
        #pragma unroll 4
        for (int j = 0; j < 64; j++) {
            float4 pa = *reinterpret_cast<float4*>(ps + j * SQ + ti * 8);
            float4 pb = *reinterpret_cast<float4*>(ps + j * SQ + ti * 8 + 4);
            float4 vb = *reinterpret_cast<float4*>(vs + j * SK + tj * 4);
            float av[8] = {pa.x, pa.y, pa.z, pa.w, pb.x, pb.y, pb.z, pb.w};
            float bv[4] = {vb.x, vb.y, vb.z, vb.w};
            #pragma unroll
            for (int r = 0; r < 8; r++)
                #pragma unroll
                for (int c = 0; c < 4; c++)
                    o[r][c] += av[r] * bv[c];
        }
    }

    __syncthreads();
    #pragma unroll
    for (int r = 0; r < 8; r++) {
        atomicAdd(&Zs[ti * 8 + r], zl[r]);
        atomicAdd(&Zms[ti * 8 + r], zml[r]);
    }
    __syncthreads();

    #pragma unroll
    for (int r = 0; r < 8; r++) {
        const int il = ti * 8 + r;
        float rn = 1.f / (Zms[il] + EPSV * Zs[il]);
        float4 w = make_float4(o[r][0] * rn, o[r][1] * rn, o[r][2] * rn, o[r][3] * rn);
        *reinterpret_cast<float4*>(
            d_z + ((size_t)(bb * LL + i0 + il)) * INNR + hh * DH + tj * 4) = w;
    }
}

// ---------------------------------------------------------------------------
// Kernel 3: out GEMM + bias.  out[4096,1024] = z[4096,1024] @ W_out + b_out
// ---------------------------------------------------------------------------
__global__ __launch_bounds__(256) void out_gemm_kernel(
    const float* __restrict__ W, const float* __restrict__ bias,
    float* __restrict__ out)
{
    __shared__ float As[16][128];
    __shared__ float Bs[16][132];

    const int tid = threadIdx.x;
    const int tx = tid & 15, ty = tid >> 4;
    const int m0 = blockIdx.y * 128;
    const int n0 = blockIdx.x * 128;

    float acc[8][8] = {};

    for (int k0 = 0; k0 < INNR; k0 += 16) {
        #pragma unroll
        for (int it = 0; it < 2; it++) {
            int s = tid + it * 256;
            int r = s >> 2, c4 = (s & 3) * 4;
            float4 f = *reinterpret_cast<const float4*>(&d_z[(m0 + r) * INNR + k0 + c4]);
            As[c4 + 0][r] = f.x; As[c4 + 1][r] = f.y;
            As[c4 + 2][r] = f.z; As[c4 + 3][r] = f.w;
        }
        #pragma unroll
        for (int it = 0; it < 2; it++) {
            int s = tid + it * 256;
            int kk = s >> 5, n4 = (s & 31) * 4;
            *reinterpret_cast<float4*>(&Bs[kk][n4]) =
                *reinterpret_cast<const float4*>(&W[(k0 + kk) * DIMK + n0 + n4]);
        }
        __syncthreads();
        #pragma unroll 4
        for (int kk = 0; kk < 16; kk++) {
            float a[8], b[8];
            float4 a0 = *reinterpret_cast<float4*>(&As[kk][ty * 8]);
            float4 a1 = *reinterpret_cast<float4*>(&As[kk][ty * 8 + 4]);
            float4 b0 = *reinterpret_cast<float4*>(&Bs[kk][tx * 8]);
            float4 b1 = *reinterpret_cast<float4*>(&Bs[kk][tx * 8 + 4]);
            a[0]=a0.x; a[1]=a0.y; a[2]=a0.z; a[3]=a0.w;
            a[4]=a1.x; a[5]=a1.y; a[6]=a1.z; a[7]=a1.w;
            b[0]=b0.x; b[1]=b0.y; b[2]=b0.z; b[3]=b0.w;
            b[4]=b1.x; b[5]=b1.y; b[6]=b1.z; b[7]=b1.w;
            #pragma unroll
            for (int i = 0; i < 8; i++)
                #pragma unroll
                for (int j = 0; j < 8; j++)
                    acc[i][j] += a[i] * b[j];
        }
        __syncthreads();
    }

    const int col0 = n0 + tx * 8;
    float4 bv0 = *reinterpret_cast<const float4*>(bias + col0);
    float4 bv1 = *reinterpret_cast<const float4*>(bias + col0 + 4);
    #pragma unroll
    for (int i = 0; i < 8; i++) {
        int row = m0 + ty * 8 + i;
        float* p = out + (size_t)row * DIMK + col0;
        *reinterpret_cast<float4*>(p) = make_float4(
            acc[i][0] + bv0.x, acc[i][1] + bv0.y, acc[i][2] + bv0.z, acc[i][3] + bv0.w);
        *reinterpret_cast<float4*>(p + 4) = make_float4(
            acc[i][4] + bv1.x, acc[i][5] + bv1.y, acc[i][6] + bv1.z, acc[i][7] + bv1.w);
    }
}

// ---------------------------------------------------------------------------
extern "C" void kernel_launch(void* const* d_in, const int* in_sizes, int n_in,
                              void* d_out, int out_size)
{
    const float* x     = (const float*)d_in[0];   // [2,2048,1024]
    const float* mask  = (const float*)d_in[1];   // [2,2048,2048]
    const float* Wqkv  = (const float*)d_in[2];   // [1024,3072]
    const float* Wout  = (const float*)d_in[3];   // [1024,1024]
    const float* bout  = (const float*)d_in[4];   // [1024]
    float* out = (float*)d_out;

    static const size_t att_smem = (size_t)ATT_SMEM_FLOATS * sizeof(float);
    cudaFuncSetAttribute(attn_kernel,
                         cudaFuncAttributeMaxDynamicSharedMemorySize, (int)att_smem);

    // 1) QKV projection: [4096,1024] @ [1024,3072]
    {
        dim3 grid(3072 / 128, 4096 / 128);
        qkv_gemm_kernel<<<grid, 256>>>(x, Wqkv);
    }
    // 2) attention
    {
        dim3 grid(LL / 128, NH, BB);
        attn_kernel<<<grid, 256, att_smem>>>(mask);
    }
    // 3) output projection + bias
    {
        dim3 grid(1024 / 128, 4096 / 128);
        out_gemm_kernel<<<grid, 256>>>(Wout, bout, out);
    }
}

// round 4
// speedup vs baseline: 2.5058x; 2.5058x over previous
#include <cuda_runtime.h>
#include <cstdint>

#define BB   2
#define LL   2048
#define DIMK 1024
#define NH   16
#define DH   64
#define INNR 1024
#define ATT_SCALE 0.125f
#define EPSV 1e-10f

// Scratch (allocation-free): q,k,v in [b][h][l][dh] (tf32-rounded), z in [b][l][inner]
__device__ __align__(256) float d_q[BB * NH * LL * DH];
__device__ __align__(256) float d_k[BB * NH * LL * DH];
__device__ __align__(256) float d_v[BB * NH * LL * DH];
__device__ __align__(256) float d_z[BB * LL * INNR];

__device__ __forceinline__ float to_tf32(float x) {
    uint32_t u;
    asm("cvt.rna.tf32.f32 %0, %1;" : "=r"(u) : "f"(x));
    return __uint_as_float(u);
}

// D += A(16x8,row) * B(8x8,col)  tf32, fp32 accum
__device__ __forceinline__ void mma8(float* d, const float* a, const float* b) {
    asm volatile(
        "mma.sync.aligned.m16n8k8.row.col.f32.tf32.tf32.f32 "
        "{%0,%1,%2,%3}, {%4,%5,%6,%7}, {%8,%9}, {%0,%1,%2,%3};"
        : "+f"(d[0]), "+f"(d[1]), "+f"(d[2]), "+f"(d[3])
        : "r"(__float_as_uint(a[0])), "r"(__float_as_uint(a[1])),
          "r"(__float_as_uint(a[2])), "r"(__float_as_uint(a[3])),
          "r"(__float_as_uint(b[0])), "r"(__float_as_uint(b[1])));
}

// ---------------------------------------------------------------------------
// GEMM: C[M,N] = A[M,K=1024] @ B[1024,N], CTA 128x128, 8 warps (2m x 4n),
// warp tile 64x32, m16n8k8 tf32 atoms. MODE 0: qkv (scatter to q/k/v, round).
// MODE 1: out-proj (A = d_z, +bias, store to outp).
// ---------------------------------------------------------------------------
template<int N, int MODE>
__global__ __launch_bounds__(256) void gemm_kernel(
    const float* __restrict__ Ain, const float* __restrict__ Bm,
    const float* __restrict__ bias, float* __restrict__ outp)
{
    __shared__ float As[128 * 36];   // [m][k], pad 36 -> (4g+t) banks distinct
    __shared__ float Bs[32 * 136];   // [k][n], pad 136 -> (8t+g) banks distinct

    const int tid = threadIdx.x, lane = tid & 31, wid = tid >> 5;
    const int wm = wid >> 2, wn = wid & 3;       // 2 x 4 warp grid
    const int g = lane >> 2, t = lane & 3;
    const int m0 = blockIdx.y * 128, n0 = blockIdx.x * 128;

    const float* A = (MODE == 0) ? Ain : d_z;

    float c[4][4][4];
    #pragma unroll
    for (int i = 0; i < 4; i++)
        #pragma unroll
        for (int j = 0; j < 4; j++)
            c[i][j][0] = c[i][j][1] = c[i][j][2] = c[i][j][3] = 0.f;

    for (int k0 = 0; k0 < DIMK; k0 += 32) {
        #pragma unroll
        for (int i = 0; i < 4; i++) {
            int slot = tid + i * 256;
            int r = slot >> 3, c4 = (slot & 7) * 4;
            float4 f = *reinterpret_cast<const float4*>(&A[(size_t)(m0 + r) * DIMK + k0 + c4]);
            *reinterpret_cast<float4*>(&As[r * 36 + c4]) =
                make_float4(to_tf32(f.x), to_tf32(f.y), to_tf32(f.z), to_tf32(f.w));
            int kk = slot >> 5, n4 = (slot & 31) * 4;
            float4 h = *reinterpret_cast<const float4*>(&Bm[(size_t)(k0 + kk) * N + n0 + n4]);
            *reinterpret_cast<float4*>(&Bs[kk * 136 + n4]) =
                make_float4(to_tf32(h.x), to_tf32(h.y), to_tf32(h.z), to_tf32(h.w));
        }
        __syncthreads();

        #pragma unroll
        for (int ks = 0; ks < 4; ks++) {
            float a[4][4], b[4][2];
            #pragma unroll
            for (int mt = 0; mt < 4; mt++) {
                int base = (wm * 64 + mt * 16 + g) * 36 + ks * 8;
                a[mt][0] = As[base + t];
                a[mt][1] = As[base + 8 * 36 + t];
                a[mt][2] = As[base + t + 4];
                a[mt][3] = As[base + 8 * 36 + t + 4];
            }
            #pragma unroll
            for (int nt = 0; nt < 4; nt++) {
                int coln = wn * 32 + nt * 8 + g;
                b[nt][0] = Bs[(ks * 8 + t) * 136 + coln];
                b[nt][1] = Bs[(ks * 8 + t + 4) * 136 + coln];
            }
            #pragma unroll
            for (int mt = 0; mt < 4; mt++)
                #pragma unroll
                for (int nt = 0; nt < 4; nt++)
                    mma8(c[mt][nt], a[mt], b[nt]);
        }
        __syncthreads();
    }

    if (MODE == 0) {
        // scatter rounded q/k/v into [b][h][l][64]
        #pragma unroll
        for (int nt = 0; nt < 4; nt++) {
            int col = n0 + wn * 32 + nt * 8 + 2 * t;
            int sec = col >> 10;
            float* dst = (sec == 0) ? d_q : ((sec == 1) ? d_k : d_v);
            int within = col & 1023;
            int hh = within >> 6, dd = within & 63;
            #pragma unroll
            for (int mt = 0; mt < 4; mt++) {
                int row0 = m0 + wm * 64 + mt * 16 + g;
                #pragma unroll
                for (int hf = 0; hf < 2; hf++) {
                    int row = row0 + hf * 8;
                    int bb = row >> 11, l = row & (LL - 1);
                    float2 w = make_float2(to_tf32(c[mt][nt][hf * 2]),
                                           to_tf32(c[mt][nt][hf * 2 + 1]));
                    *reinterpret_cast<float2*>(
                        &dst[((size_t)(bb * NH + hh) * LL + l) * DH + dd]) = w;
                }
            }
        }
    } else {
        #pragma unroll
        for (int nt = 0; nt < 4; nt++) {
            int col = n0 + wn * 32 + nt * 8 + 2 * t;
            float2 bv = *reinterpret_cast<const float2*>(&bias[col]);
            #pragma unroll
            for (int mt = 0; mt < 4; mt++) {
                int row0 = m0 + wm * 64 + mt * 16 + g;
                #pragma unroll
                for (int hf = 0; hf < 2; hf++) {
                    int row = row0 + hf * 8;
                    float2 w = make_float2(c[mt][nt][hf * 2] + bv.x,
                                           c[mt][nt][hf * 2 + 1] + bv.y);
                    *reinterpret_cast<float2*>(&outp[(size_t)row * N + col]) = w;
                }
            }
        }
    }
}

// ---------------------------------------------------------------------------
// Attention: CTA = 128 q-rows of one (b,h); KV tiles of 64; tf32 mma for
// S = QK^T and O += P V. Streaming sums (no running max):
//   z = sum(e*m*v) / (sum(e*m) + eps*sum(e))
// 8 warps as 4(m) x 2(n); warp tiles 32x32.
// ---------------------------------------------------------------------------
#define QS_S 68
#define KS_S 68
#define VS_S 72
#define PS_S 76
#define ATT_SMEM_FLOATS (128*QS_S + 64*KS_S + 64*VS_S + 128*PS_S + 256)

__global__ __launch_bounds__(256) void attn_kernel(const float* __restrict__ mask)
{
    extern __shared__ float smf[];
    float* qs  = smf;                       // [128][68]  q rows (tf32 bits)
    float* ks  = qs + 128 * QS_S;           // [64][68]   k rows
    float* vs  = ks + 64 * KS_S;            // [64][72]   v rows
    float* ps  = vs + 64 * VS_S;            // [128][76]  P rows (tf32 bits)
    float* Zs  = ps + 128 * PS_S;           // [128]
    float* Zms = Zs + 128;                  // [128]

    const int tid = threadIdx.x, lane = tid & 31, wid = tid >> 5;
    const int wm = wid >> 1, wn = wid & 1;  // 4 x 2 warp grid
    const int g = lane >> 2, t = lane & 3;
    const int i0 = blockIdx.x * 128;
    const int hh = blockIdx.y, bb = blockIdx.z;

    const float* qg = d_q + ((size_t)(bb * NH + hh) * LL + i0) * DH;
    const float* kg = d_k + ((size_t)(bb * NH + hh) * LL) * DH;
    const float* vg = d_v + ((size_t)(bb * NH + hh) * LL) * DH;
    const float* mg = mask + (size_t)bb * LL * LL + (size_t)i0 * LL;

    if (tid < 128) { Zs[tid] = 0.f; Zms[tid] = 0.f; }

    #pragma unroll
    for (int i = 0; i < 8; i++) {           // q tile 128x64
        int slot = tid + i * 256;
        int r = slot >> 4, c4 = (slot & 15) * 4;
        *reinterpret_cast<float4*>(&qs[r * QS_S + c4]) =
            *reinterpret_cast<const float4*>(&qg[(size_t)r * DH + c4]);
    }

    float o[2][4][4];
    #pragma unroll
    for (int i = 0; i < 2; i++)
        #pragma unroll
        for (int j = 0; j < 4; j++)
            o[i][j][0] = o[i][j][1] = o[i][j][2] = o[i][j][3] = 0.f;
    float zl[4] = {}, zml[4] = {};

    for (int jb = 0; jb < LL / 64; jb++) {
        const int j0 = jb * 64;
        __syncthreads();
        #pragma unroll
        for (int i = 0; i < 4; i++) {       // k,v tiles 64x64
            int slot = tid + i * 256;
            int r = slot >> 4, c4 = (slot & 15) * 4;
            *reinterpret_cast<float4*>(&ks[r * KS_S + c4]) =
                *reinterpret_cast<const float4*>(&kg[(size_t)(j0 + r) * DH + c4]);
            *reinterpret_cast<float4*>(&vs[r * VS_S + c4]) =
                *reinterpret_cast<const float4*>(&vg[(size_t)(j0 + r) * DH + c4]);
        }
        __syncthreads();

        // ---- S = Q K^T  (warp tile 32x32)
        float s[2][4][4];
        #pragma unroll
        for (int i = 0; i < 2; i++)
            #pragma unroll
            for (int j = 0; j < 4; j++)
                s[i][j][0] = s[i][j][1] = s[i][j][2] = s[i][j][3] = 0.f;

        #pragma unroll
        for (int k8 = 0; k8 < 8; k8++) {
            float a[2][4], b[4][2];
            #pragma unroll
            for (int mt = 0; mt < 2; mt++) {
                int base = (wm * 32 + mt * 16 + g) * QS_S + k8 * 8;
                a[mt][0] = qs[base + t];
                a[mt][1] = qs[base + 8 * QS_S + t];
                a[mt][2] = qs[base + t + 4];
                a[mt][3] = qs[base + 8 * QS_S + t + 4];
            }
            #pragma unroll
            for (int nt = 0; nt < 4; nt++) {
                int jr = wn * 32 + nt * 8 + g;
                b[nt][0] = ks[jr * KS_S + k8 * 8 + t];
                b[nt][1] = ks[jr * KS_S + k8 * 8 + t + 4];
            }
            #pragma unroll
            for (int mt = 0; mt < 2; mt++)
                #pragma unroll
                for (int nt = 0; nt < 4; nt++)
                    mma8(s[mt][nt], a[mt], b[nt]);
        }

        // ---- exp, mask, running sums, stage P (tf32 bits)
        #pragma unroll
        for (int mt = 0; mt < 2; mt++) {
            #pragma unroll
            for (int nt = 0; nt < 4; nt++) {
                int r0 = wm * 32 + mt * 16 + g;
                int jc = wn * 32 + nt * 8 + 2 * t;
                const float* mp = mg + (size_t)r0 * LL + j0 + jc;
                float2 mv0 = *reinterpret_cast<const float2*>(mp);
                float2 mv1 = *reinterpret_cast<const float2*>(mp + 8 * LL);
                float e00 = __expf(s[mt][nt][0] * ATT_SCALE);
                float e01 = __expf(s[mt][nt][1] * ATT_SCALE);
                float e10 = __expf(s[mt][nt][2] * ATT_SCALE);
                float e11 = __expf(s[mt][nt][3] * ATT_SCALE);
                zl[mt * 2 + 0] += e00 + e01;
                zl[mt * 2 + 1] += e10 + e11;
                float p00 = e00 * mv0.x, p01 = e01 * mv0.y;
                float p10 = e10 * mv1.x, p11 = e11 * mv1.y;
                zml[mt * 2 + 0] += p00 + p01;
                zml[mt * 2 + 1] += p10 + p11;
                *reinterpret_cast<float2*>(&ps[r0 * PS_S + jc]) =
                    make_float2(to_tf32(p00), to_tf32(p01));
                *reinterpret_cast<float2*>(&ps[(r0 + 8) * PS_S + jc]) =
                    make_float2(to_tf32(p10), to_tf32(p11));
            }
        }
        __syncthreads();

        // ---- O += P V  (warp tile 32x32 over dh)
        #pragma unroll
        for (int k8 = 0; k8 < 8; k8++) {
            float a[2][4], b[4][2];
            #pragma unroll
            for (int mt = 0; mt < 2; mt++) {
                int base = (wm * 32 + mt * 16 + g) * PS_S + k8 * 8;
                a[mt][0] = ps[base + t];
                a[mt][1] = ps[base + 8 * PS_S + t];
                a[mt][2] = ps[base + t + 4];
                a[mt][3] = ps[base + 8 * PS_S + t + 4];
            }
            #pragma unroll
            for (int nt = 0; nt < 4; nt++) {
                int dc = wn * 32 + nt * 8 + g;
                b[nt][0] = vs[(k8 * 8 + t) * VS_S + dc];
                b[nt][1] = vs[(k8 * 8 + t + 4) * VS_S + dc];
            }
            #pragma unroll
            for (int mt = 0; mt < 2; mt++)
                #pragma unroll
                for (int nt = 0; nt < 4; nt++)
                    mma8(o[mt][nt], a[mt], b[nt]);
        }
    }

    // ---- row-sum reduction: over 4 lanes of each row group, then atomics
    #pragma unroll
    for (int r = 0; r < 4; r++) {
        zl[r]  += __shfl_xor_sync(0xffffffffu, zl[r], 1);
        zl[r]  += __shfl_xor_sync(0xffffffffu, zl[r], 2);
        zml[r] += __shfl_xor_sync(0xffffffffu, zml[r], 1);
        zml[r] += __shfl_xor_sync(0xffffffffu, zml[r], 2);
    }
    if (t == 0) {
        #pragma unroll
        for (int r = 0; r < 4; r++) {
            int row = wm * 32 + (r >> 1) * 16 + g + (r & 1) * 8;
            atomicAdd(&Zs[row], zl[r]);
            atomicAdd(&Zms[row], zml[r]);
        }
    }
    __syncthreads();

    float rn[2][2];
    #pragma unroll
    for (int mt = 0; mt < 2; mt++)
        #pragma unroll
        for (int hf = 0; hf < 2; hf++) {
            int row = wm * 32 + mt * 16 + g + hf * 8;
            rn[mt][hf] = 1.f / (Zms[row] + EPSV * Zs[row]);
        }

    #pragma unroll
    for (int mt = 0; mt < 2; mt++) {
        #pragma unroll
        for (int nt = 0; nt < 4; nt++) {
            int dc = wn * 32 + nt * 8 + 2 * t;
            #pragma unroll
            for (int hf = 0; hf < 2; hf++) {
                int row = wm * 32 + mt * 16 + g + hf * 8;
                float2 w = make_float2(o[mt][nt][hf * 2] * rn[mt][hf],
                                       o[mt][nt][hf * 2 + 1] * rn[mt][hf]);
                *reinterpret_cast<float2*>(
                    &d_z[(size_t)(bb * LL + i0 + row) * INNR + hh * DH + dc]) = w;
            }
        }
    }
}

// ---------------------------------------------------------------------------
extern "C" void kernel_launch(void* const* d_in, const int* in_sizes, int n_in,
                              void* d_out, int out_size)
{
    const float* x    = (const float*)d_in[0];   // [2,2048,1024]
    const float* mask = (const float*)d_in[1];   // [2,2048,2048]
    const float* Wqkv = (const float*)d_in[2];   // [1024,3072]
    const float* Wout = (const float*)d_in[3];   // [1024,1024]
    const float* bout = (const float*)d_in[4];   // [1024]
    float* out = (float*)d_out;

    static const size_t att_smem = (size_t)ATT_SMEM_FLOATS * sizeof(float);
    cudaFuncSetAttribute(attn_kernel,
                         cudaFuncAttributeMaxDynamicSharedMemorySize, (int)att_smem);

    {   // 1) QKV projection  [4096,1024] @ [1024,3072]
        dim3 grid(3072 / 128, 4096 / 128);
        gemm_kernel<3072, 0><<<grid, 256>>>(x, Wqkv, nullptr, nullptr);
    }
    {   // 2) attention
        dim3 grid(LL / 128, NH, BB);
        attn_kernel<<<grid, 256, att_smem>>>(mask);
    }
    {   // 3) output projection + bias  [4096,1024] @ [1024,1024]
        dim3 grid(1024 / 128, 4096 / 128);
        gemm_kernel<1024, 1><<<grid, 256>>>(nullptr, Wout, bout, out);
    }
}

// round 5
// speedup vs baseline: 2.9178x; 1.1644x over previous
#include <cuda_runtime.h>
#include <cstdint>

#define BB   2
#define LL   2048
#define DIMK 1024
#define NH   16
#define DH   64
#define INNR 1024
#define ATT_SCALE 0.125f

// Scratch (allocation-free): q,k,v in [b][h][l][dh] (tf32-rounded; q pre-scaled), z in [b][l][inner]
__device__ __align__(256) float d_q[BB * NH * LL * DH];
__device__ __align__(256) float d_k[BB * NH * LL * DH];
__device__ __align__(256) float d_v[BB * NH * LL * DH];
__device__ __align__(256) float d_z[BB * LL * INNR];

__device__ __forceinline__ float to_tf32(float x) {
    uint32_t u;
    asm("cvt.rna.tf32.f32 %0, %1;" : "=r"(u) : "f"(x));
    return __uint_as_float(u);
}

// D += A(16x8,row) * B(8x8,col)  tf32, fp32 accum
__device__ __forceinline__ void mma8(float* d, const float* a, const float* b) {
    asm volatile(
        "mma.sync.aligned.m16n8k8.row.col.f32.tf32.tf32.f32 "
        "{%0,%1,%2,%3}, {%4,%5,%6,%7}, {%8,%9}, {%0,%1,%2,%3};"
        : "+f"(d[0]), "+f"(d[1]), "+f"(d[2]), "+f"(d[3])
        : "r"(__float_as_uint(a[0])), "r"(__float_as_uint(a[1])),
          "r"(__float_as_uint(a[2])), "r"(__float_as_uint(a[3])),
          "r"(__float_as_uint(b[0])), "r"(__float_as_uint(b[1])));
}

// ---------------------------------------------------------------------------
// GEMM: C[M,N] = A[M,K=1024] @ B[1024,N], CTA 128x128, 8 warps (2m x 4n),
// warp tile 64x32, m16n8k8 tf32. Double-buffered smem, reg-staged prefetch,
// ONE sync per 32-wide k-tile.
// MODE 0: qkv (scatter to q/k/v, re-round, scale q). MODE 1: out-proj.
// ---------------------------------------------------------------------------
#define GA_SZ (128 * 36)    // [m][k] pad 36
#define GB_SZ (32 * 136)    // [k][n] pad 136
#define GBUF  (GA_SZ + GB_SZ)
#define GEMM_SMEM_BYTES (2 * GBUF * sizeof(float))

template<int N, int MODE>
__global__ __launch_bounds__(256, 2) void gemm_kernel(
    const float* __restrict__ Ain, const float* __restrict__ Bm,
    const float* __restrict__ bias, float* __restrict__ outp)
{
    extern __shared__ float sm[];

    const int tid = threadIdx.x, lane = tid & 31, wid = tid >> 5;
    const int wm = wid >> 2, wn = wid & 3;       // 2 x 4 warp grid
    const int g = lane >> 2, t = lane & 3;
    const int m0 = blockIdx.y * 128, n0 = blockIdx.x * 128;

    const float* A = (MODE == 0) ? Ain : d_z;

    // staging offsets (4 slots each for A and B)
    int ar[4], ac[4], bk[4], bn[4];
    #pragma unroll
    for (int i = 0; i < 4; i++) {
        int slot = tid + i * 256;
        ar[i] = slot >> 3;  ac[i] = (slot & 7) * 4;
        bk[i] = slot >> 5;  bn[i] = (slot & 31) * 4;
    }

    float c[4][4][4];
    #pragma unroll
    for (int i = 0; i < 4; i++)
        #pragma unroll
        for (int j = 0; j < 4; j++)
            c[i][j][0] = c[i][j][1] = c[i][j][2] = c[i][j][3] = 0.f;

    float4 rA[4], rB[4];
    // prologue: tile 0 -> regs -> smem buf 0
    #pragma unroll
    for (int i = 0; i < 4; i++)
        rA[i] = *reinterpret_cast<const float4*>(&A[(size_t)(m0 + ar[i]) * DIMK + ac[i]]);
    #pragma unroll
    for (int i = 0; i < 4; i++)
        rB[i] = *reinterpret_cast<const float4*>(&Bm[(size_t)bk[i] * N + n0 + bn[i]]);
    #pragma unroll
    for (int i = 0; i < 4; i++) {
        *reinterpret_cast<float4*>(&sm[ar[i] * 36 + ac[i]]) =
            make_float4(to_tf32(rA[i].x), to_tf32(rA[i].y), to_tf32(rA[i].z), to_tf32(rA[i].w));
        *reinterpret_cast<float4*>(&sm[GA_SZ + bk[i] * 136 + bn[i]]) =
            make_float4(to_tf32(rB[i].x), to_tf32(rB[i].y), to_tf32(rB[i].z), to_tf32(rB[i].w));
    }
    __syncthreads();

    for (int kt = 0; kt < DIMK / 32; kt++) {
        float* Asb = sm + (kt & 1) * GBUF;
        float* Bsb = Asb + GA_SZ;
        float* Asn = sm + ((kt + 1) & 1) * GBUF;
        float* Bsn = Asn + GA_SZ;
        const bool pf = (kt + 1 < DIMK / 32);
        const int knext = (kt + 1) * 32;

        if (pf) {
            #pragma unroll
            for (int i = 0; i < 4; i++)
                rA[i] = *reinterpret_cast<const float4*>(
                    &A[(size_t)(m0 + ar[i]) * DIMK + knext + ac[i]]);
        }

        // mma first half (ks 0..1)
        #pragma unroll
        for (int ks = 0; ks < 2; ks++) {
            float a[4][4], b[4][2];
            #pragma unroll
            for (int mt = 0; mt < 4; mt++) {
                int base = (wm * 64 + mt * 16 + g) * 36 + ks * 8;
                a[mt][0] = Asb[base + t];
                a[mt][1] = Asb[base + 8 * 36 + t];
                a[mt][2] = Asb[base + t + 4];
                a[mt][3] = Asb[base + 8 * 36 + t + 4];
            }
            #pragma unroll
            for (int nt = 0; nt < 4; nt++) {
                int coln = wn * 32 + nt * 8 + g;
                b[nt][0] = Bsb[(ks * 8 + t) * 136 + coln];
                b[nt][1] = Bsb[(ks * 8 + t + 4) * 136 + coln];
            }
            #pragma unroll
            for (int mt = 0; mt < 4; mt++)
                #pragma unroll
                for (int nt = 0; nt < 4; nt++)
                    mma8(c[mt][nt], a[mt], b[nt]);
        }

        if (pf) {
            #pragma unroll
            for (int i = 0; i < 4; i++)
                rB[i] = *reinterpret_cast<const float4*>(
                    &Bm[(size_t)(knext + bk[i]) * N + n0 + bn[i]]);
        }

        // mma second half (ks 2..3)
        #pragma unroll
        for (int ks = 2; ks < 4; ks++) {
            float a[4][4], b[4][2];
            #pragma unroll
            for (int mt = 0; mt < 4; mt++) {
                int base = (wm * 64 + mt * 16 + g) * 36 + ks * 8;
                a[mt][0] = Asb[base + t];
                a[mt][1] = Asb[base + 8 * 36 + t];
                a[mt][2] = Asb[base + t + 4];
                a[mt][3] = Asb[base + 8 * 36 + t + 4];
            }
            #pragma unroll
            for (int nt = 0; nt < 4; nt++) {
                int coln = wn * 32 + nt * 8 + g;
                b[nt][0] = Bsb[(ks * 8 + t) * 136 + coln];
                b[nt][1] = Bsb[(ks * 8 + t + 4) * 136 + coln];
            }
            #pragma unroll
            for (int mt = 0; mt < 4; mt++)
                #pragma unroll
                for (int nt = 0; nt < 4; nt++)
                    mma8(c[mt][nt], a[mt], b[nt]);
        }

        if (pf) {
            #pragma unroll
            for (int i = 0; i < 4; i++) {
                *reinterpret_cast<float4*>(&Asn[ar[i] * 36 + ac[i]]) =
                    make_float4(to_tf32(rA[i].x), to_tf32(rA[i].y), to_tf32(rA[i].z), to_tf32(rA[i].w));
                *reinterpret_cast<float4*>(&Bsn[bk[i] * 136 + bn[i]]) =
                    make_float4(to_tf32(rB[i].x), to_tf32(rB[i].y), to_tf32(rB[i].z), to_tf32(rB[i].w));
            }
        }
        __syncthreads();
    }

    if (MODE == 0) {
        // scatter rounded q/k/v into [b][h][l][64]; q pre-scaled by 0.125
        #pragma unroll
        for (int nt = 0; nt < 4; nt++) {
            int col = n0 + wn * 32 + nt * 8 + 2 * t;
            int sec = col >> 10;
            float* dst = (sec == 0) ? d_q : ((sec == 1) ? d_k : d_v);
            float scl = (sec == 0) ? ATT_SCALE : 1.0f;
            int within = col & 1023;
            int hh = within >> 6, dd = within & 63;
            #pragma unroll
            for (int mt = 0; mt < 4; mt++) {
                int row0 = m0 + wm * 64 + mt * 16 + g;
                #pragma unroll
                for (int hf = 0; hf < 2; hf++) {
                    int row = row0 + hf * 8;
                    int bb = row >> 11, l = row & (LL - 1);
                    float2 w = make_float2(to_tf32(c[mt][nt][hf * 2]) * scl,
                                           to_tf32(c[mt][nt][hf * 2 + 1]) * scl);
                    *reinterpret_cast<float2*>(
                        &dst[((size_t)(bb * NH + hh) * LL + l) * DH + dd]) = w;
                }
            }
        }
    } else {
        #pragma unroll
        for (int nt = 0; nt < 4; nt++) {
            int col = n0 + wn * 32 + nt * 8 + 2 * t;
            float2 bv = *reinterpret_cast<const float2*>(&bias[col]);
            #pragma unroll
            for (int mt = 0; mt < 4; mt++) {
                int row0 = m0 + wm * 64 + mt * 16 + g;
                #pragma unroll
                for (int hf = 0; hf < 2; hf++) {
                    int row = row0 + hf * 8;
                    float2 w = make_float2(c[mt][nt][hf * 2] + bv.x,
                                           c[mt][nt][hf * 2 + 1] + bv.y);
                    *reinterpret_cast<float2*>(&outp[(size_t)row * N + col]) = w;
                }
            }
        }
    }
}

// ---------------------------------------------------------------------------
// Attention: CTA = 128 q-rows of one (b,h); KV tiles of 64; tf32 mma.
//   z = sum(e*m*v) / sum(e*m)      (eps*sum(e) term ~1e-10 relative: dropped)
// q pre-scaled by 0.125 so exp(s) needs no multiply.
// Mask prefetched into regs before/behind the S-matmul. Paired named barrier
// (2 warps sharing a ps row-block) instead of full CTA sync after exp.
// ---------------------------------------------------------------------------
#define QS_S 68
#define KS_S 68
#define VS_S 72
#define PS_S 76
#define ATT_SMEM_FLOATS (128*QS_S + 64*KS_S + 64*VS_S + 128*PS_S + 256)

__global__ __launch_bounds__(256, 2) void attn_kernel(const float* __restrict__ mask)
{
    extern __shared__ float smf[];
    float* qs  = smf;                       // [128][68]  q rows (tf32, pre-scaled)
    float* ks  = qs + 128 * QS_S;           // [64][68]   k rows
    float* vs  = ks + 64 * KS_S;            // [64][72]   v rows
    float* ps  = vs + 64 * VS_S;            // [128][76]  P rows (tf32)
    float* Zms = ps + 128 * PS_S;           // [128] masked row sums

    const int tid = threadIdx.x, lane = tid & 31, wid = tid >> 5;
    const int wm = wid >> 1, wn = wid & 1;  // 4 x 2 warp grid
    const int g = lane >> 2, t = lane & 3;
    const int i0 = blockIdx.x * 128;
    const int hh = blockIdx.y, bb = blockIdx.z;

    const float* qg = d_q + ((size_t)(bb * NH + hh) * LL + i0) * DH;
    const float* kg = d_k + ((size_t)(bb * NH + hh) * LL) * DH;
    const float* vg = d_v + ((size_t)(bb * NH + hh) * LL) * DH;
    const float* mg = mask + (size_t)bb * LL * LL + (size_t)i0 * LL;

    if (tid < 128) Zms[tid] = 0.f;

    #pragma unroll
    for (int i = 0; i < 8; i++) {           // q tile 128x64
        int slot = tid + i * 256;
        int r = slot >> 4, c4 = (slot & 15) * 4;
        *reinterpret_cast<float4*>(&qs[r * QS_S + c4]) =
            *reinterpret_cast<const float4*>(&qg[(size_t)r * DH + c4]);
    }

    float o[2][4][4];
    #pragma unroll
    for (int i = 0; i < 2; i++)
        #pragma unroll
        for (int j = 0; j < 4; j++)
            o[i][j][0] = o[i][j][1] = o[i][j][2] = o[i][j][3] = 0.f;
    float zml[4] = {};

    // base pointer for this thread's mask elements (row wm*32+g, col wn*32+2t)
    const float* mbase = mg + (size_t)(wm * 32 + g) * LL + wn * 32 + 2 * t;

    for (int jb = 0; jb < LL / 64; jb++) {
        const int j0 = jb * 64;
        __syncthreads();
        #pragma unroll
        for (int i = 0; i < 4; i++) {       // k,v tiles 64x64
            int slot = tid + i * 256;
            int r = slot >> 4, c4 = (slot & 15) * 4;
            *reinterpret_cast<float4*>(&ks[r * KS_S + c4]) =
                *reinterpret_cast<const float4*>(&kg[(size_t)(j0 + r) * DH + c4]);
            *reinterpret_cast<float4*>(&vs[r * VS_S + c4]) =
                *reinterpret_cast<const float4*>(&vg[(size_t)(j0 + r) * DH + c4]);
        }
        __syncthreads();

        // prefetch mask for mt=0 (rows g, g+8) — latency hidden behind S mma
        float2 m0p[4][2];
        {
            const float* mp = mbase + j0;
            #pragma unroll
            for (int nt = 0; nt < 4; nt++) {
                m0p[nt][0] = *reinterpret_cast<const float2*>(mp + nt * 8);
                m0p[nt][1] = *reinterpret_cast<const float2*>(mp + 8 * LL + nt * 8);
            }
        }

        // ---- S = Q K^T  (warp tile 32x32); q pre-scaled
        float s[2][4][4];
        #pragma unroll
        for (int i = 0; i < 2; i++)
            #pragma unroll
            for (int j = 0; j < 4; j++)
                s[i][j][0] = s[i][j][1] = s[i][j][2] = s[i][j][3] = 0.f;

        #pragma unroll
        for (int k8 = 0; k8 < 8; k8++) {
            float a[2][4], b[4][2];
            #pragma unroll
            for (int mt = 0; mt < 2; mt++) {
                int base = (wm * 32 + mt * 16 + g) * QS_S + k8 * 8;
                a[mt][0] = qs[base + t];
                a[mt][1] = qs[base + 8 * QS_S + t];
                a[mt][2] = qs[base + t + 4];
                a[mt][3] = qs[base + 8 * QS_S + t + 4];
            }
            #pragma unroll
            for (int nt = 0; nt < 4; nt++) {
                int jr = wn * 32 + nt * 8 + g;
                b[nt][0] = ks[jr * KS_S + k8 * 8 + t];
                b[nt][1] = ks[jr * KS_S + k8 * 8 + t + 4];
            }
            #pragma unroll
            for (int mt = 0; mt < 2; mt++)
                #pragma unroll
                for (int nt = 0; nt < 4; nt++)
                    mma8(s[mt][nt], a[mt], b[nt]);
        }

        // prefetch mask for mt=1 (rows g+16, g+24), consumed after mt=0 exps
        float2 m1p[4][2];
        {
            const float* mp = mbase + j0 + 16 * LL;
            #pragma unroll
            for (int nt = 0; nt < 4; nt++) {
                m1p[nt][0] = *reinterpret_cast<const float2*>(mp + nt * 8);
                m1p[nt][1] = *reinterpret_cast<const float2*>(mp + 8 * LL + nt * 8);
            }
        }

        // ---- exp, mask, masked row sums, stage P (tf32)
        #pragma unroll
        for (int mt = 0; mt < 2; mt++) {
            #pragma unroll
            for (int nt = 0; nt < 4; nt++) {
                int r0 = wm * 32 + mt * 16 + g;
                int jc = wn * 32 + nt * 8 + 2 * t;
                float2 mv0 = (mt == 0) ? m0p[nt][0] : m1p[nt][0];
                float2 mv1 = (mt == 0) ? m0p[nt][1] : m1p[nt][1];
                float e00 = __expf(s[mt][nt][0]);
                float e01 = __expf(s[mt][nt][1]);
                float e10 = __expf(s[mt][nt][2]);
                float e11 = __expf(s[mt][nt][3]);
                float p00 = e00 * mv0.x, p01 = e01 * mv0.y;
                float p10 = e10 * mv1.x, p11 = e11 * mv1.y;
                zml[mt * 2 + 0] += p00 + p01;
                zml[mt * 2 + 1] += p10 + p11;
                *reinterpret_cast<float2*>(&ps[r0 * PS_S + jc]) =
                    make_float2(to_tf32(p00), to_tf32(p01));
                *reinterpret_cast<float2*>(&ps[(r0 + 8) * PS_S + jc]) =
                    make_float2(to_tf32(p10), to_tf32(p11));
            }
        }
        // only the two warps sharing this 32-row ps block must sync
        asm volatile("bar.sync %0, 64;" :: "r"(wm + 1));

        // ---- O += P V  (warp tile 32x32 over dh)
        #pragma unroll
        for (int k8 = 0; k8 < 8; k8++) {
            float a[2][4], b[4][2];
            #pragma unroll
            for (int mt = 0; mt < 2; mt++) {
                int base = (wm * 32 + mt * 16 + g) * PS_S + k8 * 8;
                a[mt][0] = ps[base + t];
                a[mt][1] = ps[base + 8 * PS_S + t];
                a[mt][2] = ps[base + t + 4];
                a[mt][3] = ps[base + 8 * PS_S + t + 4];
            }
            #pragma unroll
            for (int nt = 0; nt < 4; nt++) {
                int dc = wn * 32 + nt * 8 + g;
                b[nt][0] = vs[(k8 * 8 + t) * VS_S + dc];
                b[nt][1] = vs[(k8 * 8 + t + 4) * VS_S + dc];
            }
            #pragma unroll
            for (int mt = 0; mt < 2; mt++)
                #pragma unroll
                for (int nt = 0; nt < 4; nt++)
                    mma8(o[mt][nt], a[mt], b[nt]);
        }
    }

    // ---- masked row-sum reduction across the 4 lanes of each row group
    #pragma unroll
    for (int r = 0; r < 4; r++) {
        zml[r] += __shfl_xor_sync(0xffffffffu, zml[r], 1);
        zml[r] += __shfl_xor_sync(0xffffffffu, zml[r], 2);
    }
    if (t == 0) {
        #pragma unroll
        for (int r = 0; r < 4; r++) {
            int row = wm * 32 + (r >> 1) * 16 + g + (r & 1) * 8;
            atomicAdd(&Zms[row], zml[r]);
        }
    }
    __syncthreads();

    float rn[2][2];
    #pragma unroll
    for (int mt = 0; mt < 2; mt++)
        #pragma unroll
        for (int hf = 0; hf < 2; hf++) {
            int row = wm * 32 + mt * 16 + g + hf * 8;
            rn[mt][hf] = 1.f / Zms[row];
        }

    #pragma unroll
    for (int mt = 0; mt < 2; mt++) {
        #pragma unroll
        for (int nt = 0; nt < 4; nt++) {
            int dc = wn * 32 + nt * 8 + 2 * t;
            #pragma unroll
            for (int hf = 0; hf < 2; hf++) {
                int row = wm * 32 + mt * 16 + g + hf * 8;
                float2 w = make_float2(o[mt][nt][hf * 2] * rn[mt][hf],
                                       o[mt][nt][hf * 2 + 1] * rn[mt][hf]);
                *reinterpret_cast<float2*>(
                    &d_z[(size_t)(bb * LL + i0 + row) * INNR + hh * DH + dc]) = w;
            }
        }
    }
}

// ---------------------------------------------------------------------------
extern "C" void kernel_launch(void* const* d_in, const int* in_sizes, int n_in,
                              void* d_out, int out_size)
{
    const float* x    = (const float*)d_in[0];   // [2,2048,1024]
    const float* mask = (const float*)d_in[1];   // [2,2048,2048]
    const float* Wqkv = (const float*)d_in[2];   // [1024,3072]
    const float* Wout = (const float*)d_in[3];   // [1024,1024]
    const float* bout = (const float*)d_in[4];   // [1024]
    float* out = (float*)d_out;

    static const size_t att_smem = (size_t)ATT_SMEM_FLOATS * sizeof(float);
    cudaFuncSetAttribute(attn_kernel,
                         cudaFuncAttributeMaxDynamicSharedMemorySize, (int)att_smem);
    cudaFuncSetAttribute(gemm_kernel<3072, 0>,
                         cudaFuncAttributeMaxDynamicSharedMemorySize, (int)GEMM_SMEM_BYTES);
    cudaFuncSetAttribute(gemm_kernel<1024, 1>,
                         cudaFuncAttributeMaxDynamicSharedMemorySize, (int)GEMM_SMEM_BYTES);

    {   // 1) QKV projection  [4096,1024] @ [1024,3072]
        dim3 grid(3072 / 128, 4096 / 128);
        gemm_kernel<3072, 0><<<grid, 256, GEMM_SMEM_BYTES>>>(x, Wqkv, nullptr, nullptr);
    }
    {   // 2) attention
        dim3 grid(LL / 128, NH, BB);
        attn_kernel<<<grid, 256, att_smem>>>(mask);
    }
    {   // 3) output projection + bias  [4096,1024] @ [1024,1024]
        dim3 grid(1024 / 128, 4096 / 128);
        gemm_kernel<1024, 1><<<grid, 256, GEMM_SMEM_BYTES>>>(nullptr, Wout, bout, out);
    }
}

// round 6
// speedup vs baseline: 3.0793x; 1.0554x over previous
#include <cuda_runtime.h>
#include <cstdint>

#define BB   2
#define LL   2048
#define DIMK 1024
#define NH   16
#define DH   64
#define INNR 1024
#define ATT_SCALE 0.125f

// Scratch (allocation-free).
// d_z triple-duty: rounded x -> (qkv reads) -> attention output -> (out-proj reads)
__device__ __align__(256) float d_q[BB * NH * LL * DH];
__device__ __align__(256) float d_k[BB * NH * LL * DH];
__device__ __align__(256) float d_v[BB * NH * LL * DH];
__device__ __align__(256) float d_z[BB * LL * INNR];
__device__ __align__(256) float d_wqr[DIMK * 3 * INNR];   // rounded W_qkv
__device__ __align__(256) float d_wor[INNR * DIMK];       // rounded W_out

__device__ __forceinline__ float to_tf32(float x) {
    uint32_t u;
    asm("cvt.rna.tf32.f32 %0, %1;" : "=r"(u) : "f"(x));
    return __uint_as_float(u);
}

// D += A(16x8,row) * B(8x8,col)  tf32, fp32 accum
__device__ __forceinline__ void mma8(float* d, const float* a, const float* b) {
    asm volatile(
        "mma.sync.aligned.m16n8k8.row.col.f32.tf32.tf32.f32 "
        "{%0,%1,%2,%3}, {%4,%5,%6,%7}, {%8,%9}, {%0,%1,%2,%3};"
        : "+f"(d[0]), "+f"(d[1]), "+f"(d[2]), "+f"(d[3])
        : "r"(__float_as_uint(a[0])), "r"(__float_as_uint(a[1])),
          "r"(__float_as_uint(a[2])), "r"(__float_as_uint(a[3])),
          "r"(__float_as_uint(b[0])), "r"(__float_as_uint(b[1])));
}

// ---------------------------------------------------------------------------
// Kernel 0: elementwise tf32 rounding
// ---------------------------------------------------------------------------
__global__ __launch_bounds__(256) void round_kernel(
    const float* __restrict__ src, float* __restrict__ dst, int n4)
{
    int i = blockIdx.x * blockDim.x + threadIdx.x;
    if (i < n4) {
        float4 f = reinterpret_cast<const float4*>(src)[i];
        reinterpret_cast<float4*>(dst)[i] =
            make_float4(to_tf32(f.x), to_tf32(f.y), to_tf32(f.z), to_tf32(f.w));
    }
}

// ---------------------------------------------------------------------------
// GEMM: C[4096,N] = A[4096,1024] @ B[1024,N].  CTA 128x128, 8 warps (2m x 4n),
// warp tile 64x32, m16n8k8 tf32. A staged in fragment-major quad layout
// (LDS.128 per fragment), B row-major padded. Double-buffered, 1 sync/k-tile.
// Inputs pre-rounded -> no cvt in staging.
// ---------------------------------------------------------------------------
#define AF_SEC  1028                 // floats per 8-wide k section (1024 + 4 pad)
#define AF_SZ   (4 * AF_SEC)         // 4112 floats
#define GB_SZ   (32 * 136)           // 4352 floats
#define GBUF    (AF_SZ + GB_SZ)      // 8464 floats
#define GEMM_SMEM_BYTES (2 * GBUF * sizeof(float))

template<int N, int MODE>
__global__ __launch_bounds__(256, 2) void gemm_kernel(
    const float* __restrict__ Bm, const float* __restrict__ bias,
    float* __restrict__ outp)
{
    extern __shared__ float sm[];

    const int tid = threadIdx.x, lane = tid & 31, wid = tid >> 5;
    const int wm = wid >> 2, wn = wid & 3;       // 2 x 4 warp grid
    const int g = lane >> 2, t = lane & 3;
    const int m0 = blockIdx.y * 128, n0 = blockIdx.x * 128;

    const float* A = d_z;                        // pre-rounded A for both modes

    // A staging: thread -> (ks, blk, g) quadset; loads 2 rows x 8 k
    const int aks = tid & 3, abg = tid >> 2, ablk = abg >> 3, ag = abg & 7;
    const int ar0 = ablk * 16 + ag;
    const float* Aptr = A + (size_t)(m0 + ar0) * DIMK + aks * 8;

    // B staging: 4 float4 slots
    int bk[4], bn[4];
    #pragma unroll
    for (int i = 0; i < 4; i++) {
        int slot = tid + i * 256;
        bk[i] = slot >> 5;  bn[i] = (slot & 31) * 4;
    }

    float c[4][4][4];
    #pragma unroll
    for (int i = 0; i < 4; i++)
        #pragma unroll
        for (int j = 0; j < 4; j++)
            c[i][j][0] = c[i][j][1] = c[i][j][2] = c[i][j][3] = 0.f;

    float4 f0, f1, f2, f3, rB[4];
    // prologue: tile 0
    f0 = *reinterpret_cast<const float4*>(Aptr);
    f1 = *reinterpret_cast<const float4*>(Aptr + 4);
    f2 = *reinterpret_cast<const float4*>(Aptr + 8 * DIMK);
    f3 = *reinterpret_cast<const float4*>(Aptr + 8 * DIMK + 4);
    #pragma unroll
    for (int i = 0; i < 4; i++)
        rB[i] = *reinterpret_cast<const float4*>(&Bm[(size_t)bk[i] * N + n0 + bn[i]]);
    {
        float4* AF = reinterpret_cast<float4*>(sm);
        int b4 = aks * (AF_SEC / 4) + ablk * 32 + ag * 4;
        AF[b4 + 0] = make_float4(f0.x, f2.x, f1.x, f3.x);
        AF[b4 + 1] = make_float4(f0.y, f2.y, f1.y, f3.y);
        AF[b4 + 2] = make_float4(f0.z, f2.z, f1.z, f3.z);
        AF[b4 + 3] = make_float4(f0.w, f2.w, f1.w, f3.w);
        float* Bs = sm + AF_SZ;
        #pragma unroll
        for (int i = 0; i < 4; i++)
            *reinterpret_cast<float4*>(&Bs[bk[i] * 136 + bn[i]]) = rB[i];
    }
    __syncthreads();

    for (int kt = 0; kt < DIMK / 32; kt++) {
        float* buf = sm + (kt & 1) * GBUF;
        const float4* AFb = reinterpret_cast<const float4*>(buf);
        const float* Bsb = buf + AF_SZ;
        float* nbuf = sm + ((kt + 1) & 1) * GBUF;
        const bool pf = (kt + 1 < DIMK / 32);
        const int knext = (kt + 1) * 32;

        if (pf) {
            const float* Ap = Aptr + knext;
            f0 = *reinterpret_cast<const float4*>(Ap);
            f1 = *reinterpret_cast<const float4*>(Ap + 4);
            f2 = *reinterpret_cast<const float4*>(Ap + 8 * DIMK);
            f3 = *reinterpret_cast<const float4*>(Ap + 8 * DIMK + 4);
        }

        #pragma unroll
        for (int ks = 0; ks < 2; ks++) {
            float4 av[4];
            float b[4][2];
            #pragma unroll
            for (int mt = 0; mt < 4; mt++)
                av[mt] = AFb[ks * (AF_SEC / 4) + (wm * 4 + mt) * 32 + g * 4 + t];
            #pragma unroll
            for (int nt = 0; nt < 4; nt++) {
                int coln = wn * 32 + nt * 8 + g;
                b[nt][0] = Bsb[(ks * 8 + t) * 136 + coln];
                b[nt][1] = Bsb[(ks * 8 + t + 4) * 136 + coln];
            }
            #pragma unroll
            for (int mt = 0; mt < 4; mt++)
                #pragma unroll
                for (int nt = 0; nt < 4; nt++)
                    mma8(c[mt][nt], reinterpret_cast<float*>(&av[mt]), b[nt]);
        }

        if (pf) {
            #pragma unroll
            for (int i = 0; i < 4; i++)
                rB[i] = *reinterpret_cast<const float4*>(
                    &Bm[(size_t)(knext + bk[i]) * N + n0 + bn[i]]);
        }

        #pragma unroll
        for (int ks = 2; ks < 4; ks++) {
            float4 av[4];
            float b[4][2];
            #pragma unroll
            for (int mt = 0; mt < 4; mt++)
                av[mt] = AFb[ks * (AF_SEC / 4) + (wm * 4 + mt) * 32 + g * 4 + t];
            #pragma unroll
            for (int nt = 0; nt < 4; nt++) {
                int coln = wn * 32 + nt * 8 + g;
                b[nt][0] = Bsb[(ks * 8 + t) * 136 + coln];
                b[nt][1] = Bsb[(ks * 8 + t + 4) * 136 + coln];
            }
            #pragma unroll
            for (int mt = 0; mt < 4; mt++)
                #pragma unroll
                for (int nt = 0; nt < 4; nt++)
                    mma8(c[mt][nt], reinterpret_cast<float*>(&av[mt]), b[nt]);
        }

        if (pf) {
            float4* AFn = reinterpret_cast<float4*>(nbuf);
            int b4 = aks * (AF_SEC / 4) + ablk * 32 + ag * 4;
            AFn[b4 + 0] = make_float4(f0.x, f2.x, f1.x, f3.x);
            AFn[b4 + 1] = make_float4(f0.y, f2.y, f1.y, f3.y);
            AFn[b4 + 2] = make_float4(f0.z, f2.z, f1.z, f3.z);
            AFn[b4 + 3] = make_float4(f0.w, f2.w, f1.w, f3.w);
            float* Bsn = nbuf + AF_SZ;
            #pragma unroll
            for (int i = 0; i < 4; i++)
                *reinterpret_cast<float4*>(&Bsn[bk[i] * 136 + bn[i]]) = rB[i];
        }
        __syncthreads();
    }

    if (MODE == 0) {
        // scatter rounded q/k/v into [b][h][l][64]; q pre-scaled by 0.125
        #pragma unroll
        for (int nt = 0; nt < 4; nt++) {
            int col = n0 + wn * 32 + nt * 8 + 2 * t;
            int sec = col >> 10;
            float* dst = (sec == 0) ? d_q : ((sec == 1) ? d_k : d_v);
            float scl = (sec == 0) ? ATT_SCALE : 1.0f;
            int within = col & 1023;
            int hh = within >> 6, dd = within & 63;
            #pragma unroll
            for (int mt = 0; mt < 4; mt++) {
                int row0 = m0 + wm * 64 + mt * 16 + g;
                #pragma unroll
                for (int hf = 0; hf < 2; hf++) {
                    int row = row0 + hf * 8;
                    int bb = row >> 11, l = row & (LL - 1);
                    float2 w = make_float2(to_tf32(c[mt][nt][hf * 2]) * scl,
                                           to_tf32(c[mt][nt][hf * 2 + 1]) * scl);
                    *reinterpret_cast<float2*>(
                        &dst[((size_t)(bb * NH + hh) * LL + l) * DH + dd]) = w;
                }
            }
        }
    } else {
        #pragma unroll
        for (int nt = 0; nt < 4; nt++) {
            int col = n0 + wn * 32 + nt * 8 + 2 * t;
            float2 bv = *reinterpret_cast<const float2*>(&bias[col]);
            #pragma unroll
            for (int mt = 0; mt < 4; mt++) {
                int row0 = m0 + wm * 64 + mt * 16 + g;
                #pragma unroll
                for (int hf = 0; hf < 2; hf++) {
                    int row = row0 + hf * 8;
                    float2 w = make_float2(c[mt][nt][hf * 2] + bv.x,
                                           c[mt][nt][hf * 2 + 1] + bv.y);
                    *reinterpret_cast<float2*>(&outp[(size_t)row * N + col]) = w;
                }
            }
        }
    }
}

// ---------------------------------------------------------------------------
// Attention: CTA = 128 q-rows of one (b,h); KV tiles of 64; tf32 mma.
//   z = sum(e*m*v) / sum(e*m)   (q pre-scaled by 0.125)
// Q and P held in fragment-major quad layout (LDS.128); K/V row-major.
// Output written tf32-rounded (out-proj stages it without cvt).
// ---------------------------------------------------------------------------
#define QF_SEC 1028
#define QF_SZ  (8 * QF_SEC)          // 8224 floats (128 x 64)
#define KT_S   68
#define VT_S   72
#define PF_SZ  (8 * QF_SEC)          // 8224 floats (128 x 64)
#define ATT_SMEM_FLOATS (QF_SZ + 64*KT_S + 64*VT_S + PF_SZ + 128)

__global__ __launch_bounds__(256, 2) void attn_kernel(const float* __restrict__ mask)
{
    extern __shared__ float smf[];
    float* QFf = smf;                       // Q fragments
    float* kts = QFf + QF_SZ;               // [64][68] k rows
    float* vts = kts + 64 * KT_S;           // [64][72] v rows
    float* PFf = vts + 64 * VT_S;           // P fragments
    float* Zms = PFf + PF_SZ;               // [128] masked row sums

    const int tid = threadIdx.x, lane = tid & 31, wid = tid >> 5;
    const int wm = wid >> 1, wn = wid & 1;  // 4 x 2 warp grid
    const int g = lane >> 2, t = lane & 3;
    const int i0 = blockIdx.x * 128;
    const int hh = blockIdx.y, bb = blockIdx.z;

    const float* qg = d_q + ((size_t)(bb * NH + hh) * LL + i0) * DH;
    const float* kg = d_k + ((size_t)(bb * NH + hh) * LL) * DH;
    const float* vg = d_v + ((size_t)(bb * NH + hh) * LL) * DH;
    const float* mg = mask + (size_t)bb * LL * LL + (size_t)i0 * LL;

    if (tid < 128) Zms[tid] = 0.f;

    // stage Q (128x64) into fragment layout: 512 quadsets / 256 threads
    {
        float4* QF = reinterpret_cast<float4*>(QFf);
        #pragma unroll
        for (int it = 0; it < 2; it++) {
            int idx = tid + it * 256;
            int qks = idx >> 6, qbg = idx & 63, qblk = qbg >> 3, qg2 = qbg & 7;
            int r0 = qblk * 16 + qg2;
            const float* Qp = qg + (size_t)r0 * DH + qks * 8;
            float4 a0 = *reinterpret_cast<const float4*>(Qp);
            float4 a1 = *reinterpret_cast<const float4*>(Qp + 4);
            float4 a2 = *reinterpret_cast<const float4*>(Qp + 8 * DH);
            float4 a3 = *reinterpret_cast<const float4*>(Qp + 8 * DH + 4);
            int b4 = qks * (QF_SEC / 4) + qblk * 32 + qg2 * 4;
            QF[b4 + 0] = make_float4(a0.x, a2.x, a1.x, a3.x);
            QF[b4 + 1] = make_float4(a0.y, a2.y, a1.y, a3.y);
            QF[b4 + 2] = make_float4(a0.z, a2.z, a1.z, a3.z);
            QF[b4 + 3] = make_float4(a0.w, a2.w, a1.w, a3.w);
        }
    }

    float o[2][4][4];
    #pragma unroll
    for (int i = 0; i < 2; i++)
        #pragma unroll
        for (int j = 0; j < 4; j++)
            o[i][j][0] = o[i][j][1] = o[i][j][2] = o[i][j][3] = 0.f;
    float zml[4] = {};

    const float* mbase = mg + (size_t)(wm * 32 + g) * LL + wn * 32 + 2 * t;
    const float4* QF4 = reinterpret_cast<const float4*>(QFf);
    const float4* PF4 = reinterpret_cast<const float4*>(PFf);

    for (int jb = 0; jb < LL / 64; jb++) {
        const int j0 = jb * 64;
        __syncthreads();
        #pragma unroll
        for (int i = 0; i < 4; i++) {       // k,v tiles 64x64 row-major
            int slot = tid + i * 256;
            int r = slot >> 4, c4 = (slot & 15) * 4;
            *reinterpret_cast<float4*>(&kts[r * KT_S + c4]) =
                *reinterpret_cast<const float4*>(&kg[(size_t)(j0 + r) * DH + c4]);
            *reinterpret_cast<float4*>(&vts[r * VT_S + c4]) =
                *reinterpret_cast<const float4*>(&vg[(size_t)(j0 + r) * DH + c4]);
        }
        __syncthreads();

        // prefetch mask for mt=0 (rows g, g+8) behind the S mma
        float2 m0p[4][2];
        {
            const float* mp = mbase + j0;
            #pragma unroll
            for (int nt = 0; nt < 4; nt++) {
                m0p[nt][0] = *reinterpret_cast<const float2*>(mp + nt * 8);
                m0p[nt][1] = *reinterpret_cast<const float2*>(mp + 8 * LL + nt * 8);
            }
        }

        // ---- S = Q K^T
        float s[2][4][4];
        #pragma unroll
        for (int i = 0; i < 2; i++)
            #pragma unroll
            for (int j = 0; j < 4; j++)
                s[i][j][0] = s[i][j][1] = s[i][j][2] = s[i][j][3] = 0.f;

        #pragma unroll
        for (int k8 = 0; k8 < 8; k8++) {
            float4 av[2];
            float b[4][2];
            #pragma unroll
            for (int mt = 0; mt < 2; mt++)
                av[mt] = QF4[k8 * (QF_SEC / 4) + (wm * 2 + mt) * 32 + g * 4 + t];
            #pragma unroll
            for (int nt = 0; nt < 4; nt++) {
                int jr = wn * 32 + nt * 8 + g;
                b[nt][0] = kts[jr * KT_S + k8 * 8 + t];
                b[nt][1] = kts[jr * KT_S + k8 * 8 + t + 4];
            }
            #pragma unroll
            for (int mt = 0; mt < 2; mt++)
                #pragma unroll
                for (int nt = 0; nt < 4; nt++)
                    mma8(s[mt][nt], reinterpret_cast<float*>(&av[mt]), b[nt]);
        }

        // prefetch mask for mt=1 (rows g+16, g+24)
        float2 m1p[4][2];
        {
            const float* mp = mbase + j0 + 16 * LL;
            #pragma unroll
            for (int nt = 0; nt < 4; nt++) {
                m1p[nt][0] = *reinterpret_cast<const float2*>(mp + nt * 8);
                m1p[nt][1] = *reinterpret_cast<const float2*>(mp + 8 * LL + nt * 8);
            }
        }

        // ---- exp, mask, row sums; write P directly in fragment layout
        #pragma unroll
        for (int mt = 0; mt < 2; mt++) {
            #pragma unroll
            for (int nt = 0; nt < 4; nt++) {
                float2 mv0 = (mt == 0) ? m0p[nt][0] : m1p[nt][0];
                float2 mv1 = (mt == 0) ? m0p[nt][1] : m1p[nt][1];
                float e00 = __expf(s[mt][nt][0]);
                float e01 = __expf(s[mt][nt][1]);
                float e10 = __expf(s[mt][nt][2]);
                float e11 = __expf(s[mt][nt][3]);
                float p00 = e00 * mv0.x, p01 = e01 * mv0.y;
                float p10 = e10 * mv1.x, p11 = e11 * mv1.y;
                zml[mt * 2 + 0] += p00 + p01;
                zml[mt * 2 + 1] += p10 + p11;
                // fragment address: ks=wn*4+nt, blk=wm*2+mt; cols 2t,2t+1
                int tp = (2 * t) & 3, half = t >> 1;
                float* pb = PFf + (wn * 4 + nt) * QF_SEC + (wm * 2 + mt) * 128
                          + g * 16 + half * 2;
                *reinterpret_cast<float2*>(pb + tp * 4) =
                    make_float2(to_tf32(p00), to_tf32(p10));
                *reinterpret_cast<float2*>(pb + (tp + 1) * 4) =
                    make_float2(to_tf32(p01), to_tf32(p11));
            }
        }
        // only the two warps sharing this 32-row block must sync
        asm volatile("bar.sync %0, 64;" :: "r"(wm + 1));

        // ---- O += P V
        #pragma unroll
        for (int k8 = 0; k8 < 8; k8++) {
            float4 av[2];
            float b[4][2];
            #pragma unroll
            for (int mt = 0; mt < 2; mt++)
                av[mt] = PF4[k8 * (QF_SEC / 4) + (wm * 2 + mt) * 32 + g * 4 + t];
            #pragma unroll
            for (int nt = 0; nt < 4; nt++) {
                int dc = wn * 32 + nt * 8 + g;
                b[nt][0] = vts[(k8 * 8 + t) * VT_S + dc];
                b[nt][1] = vts[(k8 * 8 + t + 4) * VT_S + dc];
            }
            #pragma unroll
            for (int mt = 0; mt < 2; mt++)
                #pragma unroll
                for (int nt = 0; nt < 4; nt++)
                    mma8(o[mt][nt], reinterpret_cast<float*>(&av[mt]), b[nt]);
        }
    }

    // ---- masked row-sum reduction
    #pragma unroll
    for (int r = 0; r < 4; r++) {
        zml[r] += __shfl_xor_sync(0xffffffffu, zml[r], 1);
        zml[r] += __shfl_xor_sync(0xffffffffu, zml[r], 2);
    }
    if (t == 0) {
        #pragma unroll
        for (int r = 0; r < 4; r++) {
            int row = wm * 32 + (r >> 1) * 16 + g + (r & 1) * 8;
            atomicAdd(&Zms[row], zml[r]);
        }
    }
    __syncthreads();

    float rn[2][2];
    #pragma unroll
    for (int mt = 0; mt < 2; mt++)
        #pragma unroll
        for (int hf = 0; hf < 2; hf++) {
            int row = wm * 32 + mt * 16 + g + hf * 8;
            rn[mt][hf] = 1.f / Zms[row];
        }

    #pragma unroll
    for (int mt = 0; mt < 2; mt++) {
        #pragma unroll
        for (int nt = 0; nt < 4; nt++) {
            int dc = wn * 32 + nt * 8 + 2 * t;
            #pragma unroll
            for (int hf = 0; hf < 2; hf++) {
                int row = wm * 32 + mt * 16 + g + hf * 8;
                float2 w = make_float2(to_tf32(o[mt][nt][hf * 2] * rn[mt][hf]),
                                       to_tf32(o[mt][nt][hf * 2 + 1] * rn[mt][hf]));
                *reinterpret_cast<float2*>(
                    &d_z[(size_t)(bb * LL + i0 + row) * INNR + hh * DH + dc]) = w;
            }
        }
    }
}

// ---------------------------------------------------------------------------
extern "C" void kernel_launch(void* const* d_in, const int* in_sizes, int n_in,
                              void* d_out, int out_size)
{
    const float* x    = (const float*)d_in[0];   // [2,2048,1024]
    const float* mask = (const float*)d_in[1];   // [2,2048,2048]
    const float* Wqkv = (const float*)d_in[2];   // [1024,3072]
    const float* Wout = (const float*)d_in[3];   // [1024,1024]
    const float* bout = (const float*)d_in[4];   // [1024]
    float* out = (float*)d_out;

    static const size_t att_smem = (size_t)ATT_SMEM_FLOATS * sizeof(float);
    cudaFuncSetAttribute(attn_kernel,
                         cudaFuncAttributeMaxDynamicSharedMemorySize, (int)att_smem);
    cudaFuncSetAttribute(gemm_kernel<3072, 0>,
                         cudaFuncAttributeMaxDynamicSharedMemorySize, (int)GEMM_SMEM_BYTES);
    cudaFuncSetAttribute(gemm_kernel<1024, 1>,
                         cudaFuncAttributeMaxDynamicSharedMemorySize, (int)GEMM_SMEM_BYTES);

    float* zr;  cudaGetSymbolAddress((void**)&zr,  d_z);
    float* wqr; cudaGetSymbolAddress((void**)&wqr, d_wqr);
    float* wor; cudaGetSymbolAddress((void**)&wor, d_wor);

    // 0) pre-round inputs to tf32
    round_kernel<<<(BB*LL*DIMK/4 + 255)/256, 256>>>(x, zr, BB*LL*DIMK/4);
    round_kernel<<<(DIMK*3*INNR/4 + 255)/256, 256>>>(Wqkv, wqr, DIMK*3*INNR/4);
    round_kernel<<<(INNR*DIMK/4 + 255)/256, 256>>>(Wout, wor, INNR*DIMK/4);

    {   // 1) QKV projection  [4096,1024] @ [1024,3072]
        dim3 grid(3072 / 128, 4096 / 128);
        gemm_kernel<3072, 0><<<grid, 256, GEMM_SMEM_BYTES>>>(wqr, nullptr, nullptr);
    }
    {   // 2) attention
        dim3 grid(LL / 128, NH, BB);
        attn_kernel<<<grid, 256, att_smem>>>(mask);
    }
    {   // 3) output projection + bias  [4096,1024] @ [1024,1024]
        dim3 grid(1024 / 128, 4096 / 128);
        gemm_kernel<1024, 1><<<grid, 256, GEMM_SMEM_BYTES>>>(wor, bout, out);
    }
}